// round 16
// baseline (speedup 1.0000x reference)
#include <cuda_runtime.h>
#include <cuda_fp16.h>
#include <stdint.h>

#define F    128
#define H1   64
#define H2   32
#define NC   10
#define NPB  8          // nodes per block (16 neighbor rows each)
#define THREADS 256     // 8 warps: 4(M) x 2(N)

// ---- dynamic shared layout (padded, swizzle-free) ----
#define AROW_B  272          // A-tile row stride: 17 x 16B chunks
#define HROW_B  144          // Hbuf row stride (hx kernel only)
#define SM_AHI  0            // 128 x 272B fp16 A tile (34816)
#define SM_HB   0            // Hbuf overlays A (hx kernel only)
#define SM_RBUF 34816        // 8*64*4 = 2048
#define SM_YBUF 36864        // 8*32*4 = 1024
#define SM_WCQ  37888        // 80 float4 = 1280
#define SM_TOTAL 39168       // -> 4 CTAs/SM

// precomputed W1 MMA fragments + packed W2 + per-node h_x
__device__ uint4   gBhi[8 * 4 * 32];     // [kc][ntile tp][lane]
__device__ __half2 gW2h[32 * 32];        // [jp][m]
__device__ __half2 gHx[100000 * 32];     // h_x[node][64] as half2

static __device__ __forceinline__ uint32_t sw_off(int row, int chunk) {
    return (uint32_t)row * 256u + (uint32_t)((chunk ^ (row & 7)) << 4);
}
static __device__ __forceinline__ uint32_t smem_u32(const void* p) {
    uint32_t a;
    asm("{ .reg .u64 t; cvta.to.shared.u64 t, %1; cvt.u32.u64 %0, t; }" : "=r"(a) : "l"(p));
    return a;
}
static __device__ __forceinline__ void ldsm_x4(uint32_t* r, uint32_t addr) {
    asm volatile("ldmatrix.sync.aligned.m8n8.x4.shared.b16 {%0,%1,%2,%3}, [%4];"
                 : "=r"(r[0]), "=r"(r[1]), "=r"(r[2]), "=r"(r[3]) : "r"(addr));
}
static __device__ __forceinline__ void stsm_x4(uint32_t addr, uint32_t a, uint32_t b,
                                               uint32_t c, uint32_t d) {
    asm volatile("stmatrix.sync.aligned.m8n8.x4.shared.b16 [%0], {%1,%2,%3,%4};"
                 :: "r"(addr), "r"(a), "r"(b), "r"(c), "r"(d) : "memory");
}
static __device__ __forceinline__ void mma16816(float* c, const uint32_t* a,
                                                uint32_t b0, uint32_t b1) {
    asm volatile(
        "mma.sync.aligned.m16n8k16.row.col.f32.f16.f16.f32 "
        "{%0,%1,%2,%3}, {%4,%5,%6,%7}, {%8,%9}, {%0,%1,%2,%3};"
        : "+f"(c[0]), "+f"(c[1]), "+f"(c[2]), "+f"(c[3])
        : "r"(a[0]), "r"(a[1]), "r"(a[2]), "r"(a[3]), "r"(b0), "r"(b1));
}
static __device__ __forceinline__ uint32_t pack_h2(float a, float b) {
    __half2 h = __floats2half2_rn(a, b);
    return *(const uint32_t*)&h;
}
static __device__ __forceinline__ uint2 pack4(__half h0, __half h1, __half h2, __half h3) {
    __half2 a = __halves2half2(h0, h1);
    __half2 b = __halves2half2(h2, h3);
    uint2 r;
    r.x = *(const uint32_t*)&a;
    r.y = *(const uint32_t*)&b;
    return r;
}
static __device__ __forceinline__ void norm_store(char* sm, int r, float4 v, int lane) {
    float ss = v.x * v.x + v.y * v.y + v.z * v.z + v.w * v.w;
    #pragma unroll
    for (int o = 16; o > 0; o >>= 1) ss += __shfl_xor_sync(0xffffffffu, ss, o);
    float inv = rsqrtf(fmaxf(ss, 1e-24f));
    __half h0 = __float2half_rn(v.x * inv);
    __half h1 = __float2half_rn(v.y * inv);
    __half h2 = __float2half_rn(v.z * inv);
    __half h3 = __float2half_rn(v.w * inv);
    uint32_t off = (uint32_t)r * AROW_B + (uint32_t)lane * 8u;
    *(uint2*)(sm + SM_AHI + off) = pack4(h0, h1, h2, h3);
}

// ---- init kernel ----
__global__ void gcn_init_kernel(const float* __restrict__ W1,
                                const float* __restrict__ W2)
{
    __shared__ __align__(16) char bsm[16384];
    const int tid = threadIdx.x, wid = tid >> 5, lane = tid & 31;

    const float4* W1v = (const float4*)W1;
    #pragma unroll
    for (int t = 0; t < 8; t++) {
        int gi = tid + t * 256;
        int j = gi >> 5, f4 = gi & 31;
        float4 v = W1v[gi];
        __half h0 = __float2half_rn(v.x), h1 = __float2half_rn(v.y);
        __half h2 = __float2half_rn(v.z), h3 = __float2half_rn(v.w);
        uint32_t off = sw_off(j, f4 >> 1) + (uint32_t)(f4 & 1) * 8u;
        *(uint2*)(bsm + off) = pack4(h0, h1, h2, h3);
    }
    for (int idx = tid; idx < 32 * 32; idx += 256) {
        int jp = idx >> 5, m = idx & 31;
        gW2h[idx] = __halves2half2(__float2half_rn(W2[m * H1 + 2 * jp]),
                                   __float2half_rn(W2[m * H1 + 2 * jp + 1]));
    }
    __syncthreads();

    const uint32_t sb = smem_u32(bsm);
    const int kc = wid;
    #pragma unroll
    for (int tp = 0; tp < 4; tp++) {
        int row = 16 * tp + ((lane >> 4) << 3) + (lane & 7);
        int chunk = kc * 2 + ((lane >> 3) & 1);
        uint32_t rh[4];
        ldsm_x4(rh, sb + sw_off(row, chunk));
        gBhi[(kc * 4 + tp) * 32 + lane] = make_uint4(rh[0], rh[1], rh[2], rh[3]);
    }
}

// ---- hx kernel: h_x = l2n(x) @ W1^T, 128 nodes per CTA -> gHx (uses Hbuf path) ----
__global__ __launch_bounds__(THREADS, 4) void gcn_hx_kernel(
    const float* __restrict__ x, int n)
{
    extern __shared__ char sm[];
    const uint32_t sb = smem_u32(sm);
    const int tid = threadIdx.x, wid = tid >> 5, lane = tid & 31;
    const long gbase = (long)blockIdx.x * 128;

    #pragma unroll 1
    for (int b0 = 0; b0 < 16; b0 += 4) {
        float4 q[4];
        #pragma unroll
        for (int t = 0; t < 4; t++) {
            long gr = gbase + wid + (b0 + t) * 8;
            q[t] = make_float4(0.f, 0.f, 0.f, 0.f);
            if (gr < n) q[t] = ((const float4*)(x + gr * (long)F))[lane];
        }
        #pragma unroll
        for (int t = 0; t < 4; t++)
            norm_store(sm, wid + (b0 + t) * 8, q[t], lane);
    }
    __syncthreads();

    // GEMM -> Hbuf (stmatrix), then export to gHx
    const int wm = wid >> 1, wn = wid & 1;
    float acc[2][4][4];
    #pragma unroll
    for (int m = 0; m < 2; m++)
        #pragma unroll
        for (int ntl = 0; ntl < 4; ntl++)
            acc[m][ntl][0] = acc[m][ntl][1] = acc[m][ntl][2] = acc[m][ntl][3] = 0.f;
    {
        const int arow = 32 * wm + (lane & 15);
        const int asel = lane >> 4;
        const uint4* pBhi = gBhi + (2 * wn) * 32 + lane;
        const uint32_t abase0 = sb + SM_AHI + (uint32_t)arow * AROW_B
                              + (uint32_t)asel * 16u;
        #pragma unroll
        for (int kc = 0; kc < 8; kc++) {
            uint4 bh0 = pBhi[kc * 128];
            uint4 bh1 = pBhi[kc * 128 + 32];
            uint32_t ahi[2][4];
            #pragma unroll
            for (int m = 0; m < 2; m++)
                ldsm_x4(ahi[m], abase0 + (uint32_t)(16 * m) * AROW_B
                                      + (uint32_t)kc * 32u);
            #pragma unroll
            for (int m = 0; m < 2; m++) {
                mma16816(acc[m][0], ahi[m], bh0.x, bh0.y);
                mma16816(acc[m][1], ahi[m], bh0.z, bh0.w);
                mma16816(acc[m][2], ahi[m], bh1.x, bh1.y);
                mma16816(acc[m][3], ahi[m], bh1.z, bh1.w);
            }
        }
    }
    __syncthreads();
    {
        const int g = lane >> 3;
        const int mrow = lane & 7;
        #pragma unroll
        for (int m = 0; m < 2; m++) {
            int R = 32 * wm + 16 * m + (g & 1) * 8 + mrow;
            #pragma unroll
            for (int h = 0; h < 2; h++) {
                int ntl_g = h * 2 + (g >> 1);
                int chunk = 4 * wn + ntl_g;
                uint32_t addr = sb + SM_HB + (uint32_t)R * HROW_B
                              + (uint32_t)chunk * 16u;
                stsm_x4(addr,
                        pack_h2(acc[m][h * 2 + 0][0], acc[m][h * 2 + 0][1]),
                        pack_h2(acc[m][h * 2 + 0][2], acc[m][h * 2 + 0][3]),
                        pack_h2(acc[m][h * 2 + 1][0], acc[m][h * 2 + 1][1]),
                        pack_h2(acc[m][h * 2 + 1][2], acc[m][h * 2 + 1][3]));
            }
        }
    }
    __syncthreads();

    #pragma unroll 1
    for (int t = 0; t < 16; t++) {
        int r = wid + t * 8;
        long gr = gbase + r;
        if (gr < n) {
            __half2 v = *(const __half2*)(sm + SM_HB + (uint32_t)r * HROW_B
                                          + (uint32_t)lane * 4u);
            gHx[gr * 32 + lane] = v;
        }
    }
}

// ---- main kernel: GEMM + in-register relu-reduction (no Hbuf) ----
__global__ __launch_bounds__(THREADS, 4) void gcn_mma_kernel(
    const float* __restrict__ nb,
    const float* __restrict__ Wc, float* __restrict__ out, int n)
{
    extern __shared__ char sm[];
    const uint32_t sb = smem_u32(sm);
    const int tid = threadIdx.x, wid = tid >> 5, lane = tid & 31;
    const long gbase = (long)blockIdx.x * NPB;

    if (tid < 80) {
        int mq = tid / 10, c = tid - mq * 10;
        const float* w = Wc + c * H2 + mq * 4;
        ((float4*)(sm + SM_WCQ))[tid] = make_float4(w[0], w[1], w[2], w[3]);
    }

    // A rows (neighbors): warp w owns rows w + 8t (t<16), 4 batches of 4
    #pragma unroll 1
    for (int b0 = 0; b0 < 16; b0 += 4) {
        float4 q[4];
        #pragma unroll
        for (int t = 0; t < 4; t++) {
            int r = wid + (b0 + t) * 8;
            long gnode = gbase + (r >> 4);
            q[t] = make_float4(0.f, 0.f, 0.f, 0.f);
            if (gnode < n)
                q[t] = ((const float4*)(nb + (gnode * 16 + (r & 15)) * (long)F))[lane];
        }
        #pragma unroll
        for (int t = 0; t < 4; t++)
            norm_store(sm, wid + (b0 + t) * 8, q[t], lane);
    }
    __syncthreads();

    // GEMM: warp grid 4(M) x 2(N); warp tile M=32 x N=32
    const int wm = wid >> 1, wn = wid & 1;
    float acc[2][4][4];
    #pragma unroll
    for (int m = 0; m < 2; m++)
        #pragma unroll
        for (int ntl = 0; ntl < 4; ntl++)
            acc[m][ntl][0] = acc[m][ntl][1] = acc[m][ntl][2] = acc[m][ntl][3] = 0.f;
    {
        const int arow = 32 * wm + (lane & 15);
        const int asel = lane >> 4;
        const uint4* pBhi = gBhi + (2 * wn) * 32 + lane;
        const uint32_t abase0 = sb + SM_AHI + (uint32_t)arow * AROW_B
                              + (uint32_t)asel * 16u;
        #pragma unroll
        for (int kc = 0; kc < 8; kc++) {
            uint4 bh0 = pBhi[kc * 128];
            uint4 bh1 = pBhi[kc * 128 + 32];
            uint32_t ahi[2][4];
            #pragma unroll
            for (int m = 0; m < 2; m++)
                ldsm_x4(ahi[m], abase0 + (uint32_t)(16 * m) * AROW_B
                                      + (uint32_t)kc * 32u);
            #pragma unroll
            for (int m = 0; m < 2; m++) {
                mma16816(acc[m][0], ahi[m], bh0.x, bh0.y);
                mma16816(acc[m][1], ahi[m], bh0.z, bh0.w);
                mma16816(acc[m][2], ahi[m], bh1.x, bh1.y);
                mma16816(acc[m][3], ahi[m], bh1.z, bh1.w);
            }
        }
    }

    // ---- in-register relu-reduction: r[node][c] = sum over 16 rows ----
    // warp (wm,wn) owns nodes 2wm,2wm+1 x cols 32wn..+31.
    // thread frag: rows (lane>>2)+{0,8}, cols C=32wn+8ntl+(lane&3)*2, C+1.
    {
        float* rbuf = (float*)(sm + SM_RBUF);
        #pragma unroll
        for (int m = 0; m < 2; m++) {
            long node = gbase + 2 * wm + m;
            if (node > (long)n - 1) node = (long)n - 1;   // clamp (n%8==0 normally)
            #pragma unroll
            for (int ntl = 0; ntl < 4; ntl++) {
                float2 hx = __half22float2(
                    gHx[node * 32 + 16 * wn + 4 * ntl + (lane & 3)]);
                float s0 = fmaxf(hx.x + acc[m][ntl][0], 0.f)
                         + fmaxf(hx.x + acc[m][ntl][2], 0.f);
                float s1 = fmaxf(hx.y + acc[m][ntl][1], 0.f)
                         + fmaxf(hx.y + acc[m][ntl][3], 0.f);
                #pragma unroll
                for (int o = 4; o < 32; o <<= 1) {
                    s0 += __shfl_xor_sync(0xffffffffu, s0, o);
                    s1 += __shfl_xor_sync(0xffffffffu, s1, o);
                }
                if (lane < 4) {
                    *(float2*)(rbuf + (2 * wm + m) * 64 + 32 * wn + 8 * ntl + lane * 2)
                        = make_float2(s0, s1);
                }
            }
        }
    }
    __syncthreads();

    // ---- per-node epilogue: warp = node (8 warps) ----
    long gnode = gbase + wid;
    if (gnode < n) {
        const float* rb = (const float*)(sm + SM_RBUF) + wid * 64;
        const float4* rb4 = (const float4*)rb;
        const __half2* w2 = gW2h + lane;
        float y = 0.f;
        #pragma unroll
        for (int jq = 0; jq < 16; jq++) {
            float4 r4 = rb4[jq];
            __half2 wa = w2[(2 * jq) * 32];
            __half2 wb = w2[(2 * jq + 1) * 32];
            y += r4.x * __low2float(wa) + r4.y * __high2float(wa)
               + r4.z * __low2float(wb) + r4.w * __high2float(wb);
        }
        y = fmaxf(y, 0.f);
        float* yb = (float*)(sm + SM_YBUF) + wid * 32;
        yb[lane] = y;
        __syncwarp();

        if (lane < NC) {
            const float4* yb4 = (const float4*)yb;
            const float4* wcq = (const float4*)(sm + SM_WCQ);
            float o = 0.f;
            #pragma unroll
            for (int mq = 0; mq < 8; mq++) {
                float4 y4 = yb4[mq];
                float4 w4 = wcq[mq * 10 + lane];
                o += y4.x * w4.x + y4.y * w4.y + y4.z * w4.z + y4.w * w4.w;
            }
            out[gnode * NC + lane] = o;
        }
    }
}

extern "C" void kernel_launch(void* const* d_in, const int* in_sizes, int n_in,
                              void* d_out, int out_size)
{
    const float* x  = (const float*)d_in[0];
    const float* nb = (const float*)d_in[1];
    const float* W1 = (const float*)d_in[2];
    const float* W2 = (const float*)d_in[3];
    const float* Wc = (const float*)d_in[4];
    float* out = (float*)d_out;

    int n = in_sizes[0] / F;
    gcn_init_kernel<<<1, 256>>>(W1, W2);
    cudaFuncSetAttribute(gcn_hx_kernel,
                         cudaFuncAttributeMaxDynamicSharedMemorySize, SM_TOTAL);
    cudaFuncSetAttribute(gcn_mma_kernel,
                         cudaFuncAttributeMaxDynamicSharedMemorySize, SM_TOTAL);
    gcn_hx_kernel<<<(n + 127) / 128, THREADS, SM_TOTAL>>>(x, n);
    int grid = (n + NPB - 1) / NPB;
    gcn_mma_kernel<<<grid, THREADS, SM_TOTAL>>>(nb, Wc, out, n);
}

// round 17
// speedup vs baseline: 1.0978x; 1.0978x over previous
#include <cuda_runtime.h>
#include <cuda_fp16.h>
#include <stdint.h>

#define F    128
#define H1   64
#define H2   32
#define NC   10
#define NPB  8          // nodes per block (16 neighbor rows each)
#define THREADS 256     // 8 warps: 4(M) x 2(N)

// ---- dynamic shared layout (padded, swizzle-free) ----
#define AROW_B  272          // A-tile row stride: 17 x 16B chunks (16 data + 1 pad)
#define HROW_B  144          // Hbuf row stride: 9 x 16B chunks (8 data + 1 pad)
#define SM_AHI  0            // 128 x 272B fp16 A tile (34816)
#define SM_HB   0            // 128 x 144B fp16 Hbuf (18432) overlays A after GEMM
#define SM_RBUF 34816        // 8*64*4 = 2048
#define SM_YBUF 36864        // 8*32*4 = 1024
#define SM_WCQ  37888        // 80 float4 = 1280
#define SM_TOTAL 39168       // -> 4 CTAs/SM (smem & 64-reg cap)

// precomputed W1 MMA fragments + packed W2 + per-node h_x
__device__ uint4   gBhi[8 * 4 * 32];     // [kc][ntile tp][lane]
__device__ __half2 gW2h[32 * 32];        // [jp][m] = (W2[m][2jp], W2[m][2jp+1])
__device__ __half2 gHx[100000 * 32];     // h_x[node][64] as half2 (12.8 MB)

// init-kernel-only swizzled layout (row stride 256B, chunk ^= row&7)
static __device__ __forceinline__ uint32_t sw_off(int row, int chunk) {
    return (uint32_t)row * 256u + (uint32_t)((chunk ^ (row & 7)) << 4);
}
static __device__ __forceinline__ uint32_t smem_u32(const void* p) {
    uint32_t a;
    asm("{ .reg .u64 t; cvta.to.shared.u64 t, %1; cvt.u32.u64 %0, t; }" : "=r"(a) : "l"(p));
    return a;
}
static __device__ __forceinline__ void ldsm_x4(uint32_t* r, uint32_t addr) {
    asm volatile("ldmatrix.sync.aligned.m8n8.x4.shared.b16 {%0,%1,%2,%3}, [%4];"
                 : "=r"(r[0]), "=r"(r[1]), "=r"(r[2]), "=r"(r[3]) : "r"(addr));
}
static __device__ __forceinline__ void stsm_x4(uint32_t addr, uint32_t a, uint32_t b,
                                               uint32_t c, uint32_t d) {
    asm volatile("stmatrix.sync.aligned.m8n8.x4.shared.b16 [%0], {%1,%2,%3,%4};"
                 :: "r"(addr), "r"(a), "r"(b), "r"(c), "r"(d) : "memory");
}
static __device__ __forceinline__ void mma16816(float* c, const uint32_t* a,
                                                uint32_t b0, uint32_t b1) {
    asm volatile(
        "mma.sync.aligned.m16n8k16.row.col.f32.f16.f16.f32 "
        "{%0,%1,%2,%3}, {%4,%5,%6,%7}, {%8,%9}, {%0,%1,%2,%3};"
        : "+f"(c[0]), "+f"(c[1]), "+f"(c[2]), "+f"(c[3])
        : "r"(a[0]), "r"(a[1]), "r"(a[2]), "r"(a[3]), "r"(b0), "r"(b1));
}
static __device__ __forceinline__ uint32_t pack_h2(float a, float b) {
    __half2 h = __floats2half2_rn(a, b);
    return *(const uint32_t*)&h;
}
static __device__ __forceinline__ uint2 pack4(__half h0, __half h1, __half h2, __half h3) {
    __half2 a = __halves2half2(h0, h1);
    __half2 b = __halves2half2(h2, h3);
    uint2 r;
    r.x = *(const uint32_t*)&a;
    r.y = *(const uint32_t*)&b;
    return r;
}
// normalize+split one row (4 floats per lane), store to padded A-tile
static __device__ __forceinline__ void norm_store(char* sm, int r, float4 v, int lane) {
    float ss = v.x * v.x + v.y * v.y + v.z * v.z + v.w * v.w;
    #pragma unroll
    for (int o = 16; o > 0; o >>= 1) ss += __shfl_xor_sync(0xffffffffu, ss, o);
    float inv = rsqrtf(fmaxf(ss, 1e-24f));
    __half h0 = __float2half_rn(v.x * inv);
    __half h1 = __float2half_rn(v.y * inv);
    __half h2 = __float2half_rn(v.z * inv);
    __half h3 = __float2half_rn(v.w * inv);
    uint32_t off = (uint32_t)r * AROW_B + (uint32_t)lane * 8u;
    *(uint2*)(sm + SM_AHI + off) = pack4(h0, h1, h2, h3);
}

// ---- init kernel: W1 fp16 fragments (replaying the ldsm path) + packed W2 ----
__global__ void gcn_init_kernel(const float* __restrict__ W1,
                                const float* __restrict__ W2)
{
    __shared__ __align__(16) char bsm[16384];    // BHI (swizzled, init-local)
    const int tid = threadIdx.x, wid = tid >> 5, lane = tid & 31;

    const float4* W1v = (const float4*)W1;
    #pragma unroll
    for (int t = 0; t < 8; t++) {
        int gi = tid + t * 256;          // gi = j*32 + f4
        int j = gi >> 5, f4 = gi & 31;
        float4 v = W1v[gi];
        __half h0 = __float2half_rn(v.x), h1 = __float2half_rn(v.y);
        __half h2 = __float2half_rn(v.z), h3 = __float2half_rn(v.w);
        uint32_t off = sw_off(j, f4 >> 1) + (uint32_t)(f4 & 1) * 8u;
        *(uint2*)(bsm + off) = pack4(h0, h1, h2, h3);
    }
    for (int idx = tid; idx < 32 * 32; idx += 256) {
        int jp = idx >> 5, m = idx & 31;
        gW2h[idx] = __halves2half2(__float2half_rn(W2[m * H1 + 2 * jp]),
                                   __float2half_rn(W2[m * H1 + 2 * jp + 1]));
    }
    __syncthreads();

    const uint32_t sb = smem_u32(bsm);
    const int kc = wid;                  // warp w -> k-chunk w
    #pragma unroll
    for (int tp = 0; tp < 4; tp++) {
        int row = 16 * tp + ((lane >> 4) << 3) + (lane & 7);
        int chunk = kc * 2 + ((lane >> 3) & 1);
        uint32_t rh[4];
        ldsm_x4(rh, sb + sw_off(row, chunk));
        gBhi[(kc * 4 + tp) * 32 + lane] = make_uint4(rh[0], rh[1], rh[2], rh[3]);
    }
}

// ---- shared GEMM body: A-tile(smem) x gBhi -> fp16 Hbuf (stmatrix) ----
static __device__ __forceinline__ void gemm_to_hbuf(char* sm, uint32_t sb,
                                                    int wid, int lane) {
    const int wm = wid >> 1, wn = wid & 1;
    float acc[2][4][4];
    #pragma unroll
    for (int m = 0; m < 2; m++)
        #pragma unroll
        for (int ntl = 0; ntl < 4; ntl++)
            acc[m][ntl][0] = acc[m][ntl][1] = acc[m][ntl][2] = acc[m][ntl][3] = 0.f;

    {
        const int arow = 32 * wm + (lane & 15);
        const int asel = lane >> 4;
        const int tpb = 2 * wn;
        const uint4* pBhi = gBhi + tpb * 32 + lane;
        const uint32_t abase0 = sb + SM_AHI + (uint32_t)arow * AROW_B
                              + (uint32_t)asel * 16u;

        #pragma unroll
        for (int kc = 0; kc < 8; kc++) {
            uint4 bh0 = pBhi[kc * 128];
            uint4 bh1 = pBhi[kc * 128 + 32];
            uint32_t ahi[2][4];
            #pragma unroll
            for (int m = 0; m < 2; m++)
                ldsm_x4(ahi[m], abase0 + (uint32_t)(16 * m) * AROW_B
                                      + (uint32_t)kc * 32u);
            #pragma unroll
            for (int m = 0; m < 2; m++) {
                mma16816(acc[m][0], ahi[m], bh0.x, bh0.y);
                mma16816(acc[m][1], ahi[m], bh0.z, bh0.w);
                mma16816(acc[m][2], ahi[m], bh1.x, bh1.y);
                mma16816(acc[m][3], ahi[m], bh1.z, bh1.w);
            }
        }
    }
    __syncthreads();   // A tile dead; fp16 Hbuf overlays it

    // C frags -> fp16 Hbuf via stmatrix
    {
        const int g = lane >> 3;
        const int mrow = lane & 7;
        #pragma unroll
        for (int m = 0; m < 2; m++) {
            int R = 32 * wm + 16 * m + (g & 1) * 8 + mrow;
            #pragma unroll
            for (int h = 0; h < 2; h++) {
                int ntl_g = h * 2 + (g >> 1);
                int chunk = 4 * wn + ntl_g;
                uint32_t addr = sb + SM_HB + (uint32_t)R * HROW_B
                              + (uint32_t)chunk * 16u;
                stsm_x4(addr,
                        pack_h2(acc[m][h * 2 + 0][0], acc[m][h * 2 + 0][1]),
                        pack_h2(acc[m][h * 2 + 0][2], acc[m][h * 2 + 0][3]),
                        pack_h2(acc[m][h * 2 + 1][0], acc[m][h * 2 + 1][1]),
                        pack_h2(acc[m][h * 2 + 1][2], acc[m][h * 2 + 1][3]));
            }
        }
    }
    __syncthreads();
}

// ---- hx kernel: h_x = l2n(x) @ W1^T for 128 nodes per CTA -> gHx ----
__global__ __launch_bounds__(THREADS, 4) void gcn_hx_kernel(
    const float* __restrict__ x, int n)
{
    extern __shared__ char sm[];
    const uint32_t sb = smem_u32(sm);
    const int tid = threadIdx.x, wid = tid >> 5, lane = tid & 31;
    const long gbase = (long)blockIdx.x * 128;

    // A rows: warp w owns rows w + 8t (t<16), 2 batches of 8 (MLP=8)
    #pragma unroll 1
    for (int b0 = 0; b0 < 16; b0 += 8) {
        float4 q[8];
        #pragma unroll
        for (int t = 0; t < 8; t++) {
            long gr = gbase + wid + (b0 + t) * 8;
            q[t] = make_float4(0.f, 0.f, 0.f, 0.f);
            if (gr < n) q[t] = ((const float4*)(x + gr * (long)F))[lane];
        }
        #pragma unroll
        for (int t = 0; t < 8; t++)
            norm_store(sm, wid + (b0 + t) * 8, q[t], lane);
    }
    __syncthreads();

    gemm_to_hbuf(sm, sb, wid, lane);

    // write Hbuf rows -> gHx (coalesced half2 per lane)
    #pragma unroll 1
    for (int t = 0; t < 16; t++) {
        int r = wid + t * 8;
        long gr = gbase + r;
        if (gr < n) {
            __half2 v = *(const __half2*)(sm + SM_HB + (uint32_t)r * HROW_B
                                          + (uint32_t)lane * 4u);
            gHx[gr * 32 + lane] = v;
        }
    }
}

// ---- main kernel: 8 nodes x 16 neighbors per CTA ----
__global__ __launch_bounds__(THREADS, 4) void gcn_mma_kernel(
    const float* __restrict__ nb,
    const float* __restrict__ Wc, float* __restrict__ out, int n)
{
    extern __shared__ char sm[];
    const uint32_t sb = smem_u32(sm);
    const int tid = threadIdx.x, wid = tid >> 5, lane = tid & 31;
    const long gbase = (long)blockIdx.x * NPB;

    // WCQ[mq*10+c] = float4 of Wc[c][mq*4 .. +3]
    if (tid < 80) {
        int mq = tid / 10, c = tid - mq * 10;
        const float* w = Wc + c * H2 + mq * 4;
        ((float4*)(sm + SM_WCQ))[tid] = make_float4(w[0], w[1], w[2], w[3]);
    }

    // A rows (all neighbors): warp w owns rows w + 8t (t<16), 2 batches of 8
    #pragma unroll 1
    for (int b0 = 0; b0 < 16; b0 += 8) {
        float4 q[8];
        #pragma unroll
        for (int t = 0; t < 8; t++) {
            int r = wid + (b0 + t) * 8;
            long gnode = gbase + (r >> 4);
            q[t] = make_float4(0.f, 0.f, 0.f, 0.f);
            if (gnode < n)
                q[t] = ((const float4*)(nb + (gnode * 16 + (r & 15)) * (long)F))[lane];
        }
        #pragma unroll
        for (int t = 0; t < 8; t++)
            norm_store(sm, wid + (b0 + t) * 8, q[t], lane);
    }
    __syncthreads();

    gemm_to_hbuf(sm, sb, wid, lane);

    // per-node epilogue: warp = node (8 warps)
    long gnode = gbase + wid;
    if (gnode < n) {
        // stage 1: lane owns col-pair (2*lane, 2*lane+1); hx from gmem
        float2 hx = __half22float2(gHx[gnode * 32 + lane]);
        const char* hp = sm + SM_HB + (uint32_t)(wid * 16) * HROW_B
                       + (uint32_t)lane * 4u;
        float r0 = 0.f, r1 = 0.f;
        #pragma unroll
        for (int k = 0; k < 16; k++) {
            float2 h = __half22float2(*(const __half2*)hp);
            hp += HROW_B;
            r0 += fmaxf(hx.x + h.x, 0.f);
            r1 += fmaxf(hx.y + h.y, 0.f);
        }
        float* rb = (float*)(sm + SM_RBUF) + wid * 64;
        ((float2*)rb)[lane] = make_float2(r0, r1);
        __syncwarp();

        // stage 2: y[lane] = relu(sum_j r[j] * W2[lane][j])
        const float4* rb4 = (const float4*)rb;
        const __half2* w2 = gW2h + lane;
        float y = 0.f;
        #pragma unroll
        for (int jq = 0; jq < 16; jq++) {
            float4 r4 = rb4[jq];
            __half2 wa = w2[(2 * jq) * 32];
            __half2 wb = w2[(2 * jq + 1) * 32];
            y += r4.x * __low2float(wa) + r4.y * __high2float(wa)
               + r4.z * __low2float(wb) + r4.w * __high2float(wb);
        }
        y = fmaxf(y, 0.f);
        float* yb = (float*)(sm + SM_YBUF) + wid * 32;
        yb[lane] = y;
        __syncwarp();

        // stage 3: out[c] = sum_m y[m] * Wc[c][m]
        if (lane < NC) {
            const float4* yb4 = (const float4*)yb;
            const float4* wcq = (const float4*)(sm + SM_WCQ);
            float o = 0.f;
            #pragma unroll
            for (int mq = 0; mq < 8; mq++) {
                float4 y4 = yb4[mq];
                float4 w4 = wcq[mq * 10 + lane];
                o += y4.x * w4.x + y4.y * w4.y + y4.z * w4.z + y4.w * w4.w;
            }
            out[gnode * NC + lane] = o;
        }
    }
}

extern "C" void kernel_launch(void* const* d_in, const int* in_sizes, int n_in,
                              void* d_out, int out_size)
{
    const float* x  = (const float*)d_in[0];
    const float* nb = (const float*)d_in[1];
    const float* W1 = (const float*)d_in[2];
    const float* W2 = (const float*)d_in[3];
    const float* Wc = (const float*)d_in[4];
    float* out = (float*)d_out;

    int n = in_sizes[0] / F;
    gcn_init_kernel<<<1, 256>>>(W1, W2);
    cudaFuncSetAttribute(gcn_hx_kernel,
                         cudaFuncAttributeMaxDynamicSharedMemorySize, SM_TOTAL);
    cudaFuncSetAttribute(gcn_mma_kernel,
                         cudaFuncAttributeMaxDynamicSharedMemorySize, SM_TOTAL);
    gcn_hx_kernel<<<(n + 127) / 128, THREADS, SM_TOTAL>>>(x, n);
    int grid = (n + NPB - 1) / NPB;
    gcn_mma_kernel<<<grid, THREADS, SM_TOTAL>>>(nb, Wc, out, n);
}